// round 14
// baseline (speedup 1.0000x reference)
#include <cuda_runtime.h>
#include <cuda_bf16.h>
#include <cstdint>

// Problem constants
#define NN     2048
#define FC     1024
#define CUBE_K 3200
#define EGO_K  3712   // EGO + RNN
#define RNN2_K 1024   // 2*RNN
#define ROOM_K 8192   // 8*FC
#define DIST_K 2048   // 2*FC

// ---------------- scratch (device globals; no allocation) ----------------
__device__ float g_hc[16384 * 1024];
__device__ float g_hd[6144 * 1024];
__device__ float g_xd[2048 * 2048];
__device__ float g_h_rnn[2048 * 1024];
__device__ float g_h_room[2048 * 1024];
__device__ float g_h_dist[2048 * 1024];
__device__ int   g_perm_rnn[NN];
__device__ int   g_perm_room[NN];
__device__ int   g_perm_dist[NN];
__device__ int   g_starts_rnn[8];
__device__ int   g_starts_room[8];
__device__ int   g_starts_dist[8];

// ---------------- routing: counting sort in one block ----------------
__global__ void route_kernel(const int* __restrict__ eid, int n, int E,
                             int* __restrict__ perm, int* __restrict__ starts)
{
    __shared__ int cnt[4];
    __shared__ int off[4];
    int tid = threadIdx.x;
    if (tid < 4) cnt[tid] = 0;
    __syncthreads();
    for (int i = tid; i < n; i += blockDim.x)
        atomicAdd(&cnt[eid[i]], 1);
    __syncthreads();
    if (tid == 0) {
        int s = 0;
        for (int e = 0; e < E; e++) { off[e] = s; starts[e] = s; s += cnt[e]; }
        starts[E] = s;
    }
    __syncthreads();
    for (int i = tid; i < n; i += blockDim.x) {
        int pos = atomicAdd(&off[eid[i]], 1);
        perm[pos] = i;
    }
}

// ---------------- helpers ----------------
__device__ __forceinline__ uint32_t smem_u32(const void* p) {
    uint32_t a;
    asm("{ .reg .u64 t; cvta.to.shared.u64 t, %1; cvt.u32.u64 %0, t; }" : "=r"(a) : "l"(p));
    return a;
}

__device__ __forceinline__ uint32_t f2tf32(float x) {
    uint32_t r;
    asm("cvt.rna.tf32.f32 %0, %1;" : "=r"(r) : "f"(x));
    return r;
}

__device__ __forceinline__ void cp16(uint32_t dst, const void* src, uint32_t srcsize) {
    asm volatile("cp.async.ca.shared.global [%0], [%1], 16, %2;"
                 :: "r"(dst), "l"(src), "r"(srcsize) : "memory");
}
#define CP_COMMIT() asm volatile("cp.async.commit_group;" ::: "memory")
#define CP_WAIT2()  asm volatile("cp.async.wait_group 2;" ::: "memory")

__device__ __forceinline__ void mma_tf32(float c[4], uint32_t a0, uint32_t a1,
                                         uint32_t a2, uint32_t a3,
                                         uint32_t b0, uint32_t b1)
{
    asm volatile(
        "mma.sync.aligned.m16n8k8.row.col.f32.tf32.tf32.f32 "
        "{%0,%1,%2,%3}, {%4,%5,%6,%7}, {%8,%9}, {%0,%1,%2,%3};"
        : "+f"(c[0]), "+f"(c[1]), "+f"(c[2]), "+f"(c[3])
        : "r"(a0), "r"(a1), "r"(a2), "r"(a3), "r"(b0), "r"(b1));
}

// ---------------- tf32 tensor-core GEMM with cp.async pipeline ----------------
// CTA tile 128x256, BK=16, 4-stage cp.async pipeline, 256 threads = 8 warps
// (2 M x 4 N), warp tile 64x64 (4 m-tiles x 8 n-tiles of m16n8k8).
// A smem: [m][k] stride 20 (bank-perfect for fragment loads).
// B smem: [k][n] stride 264.
#define BM 128
#define BN 256
#define BK 16
#define ASTR 20
#define BSTR 264
#define STAGES 4
#define AW (BM * ASTR)            // words per A stage = 2560
#define BW (BK * BSTR)            // words per B stage = 4224
#define SMEM_BYTES ((AW + BW) * STAGES * 4)   // 108544

extern __shared__ float smem_dyn[];

__global__ void __launch_bounds__(256)
tf32gemm_bias_relu(const float* __restrict__ A, const float* __restrict__ Bw,
                   const float* __restrict__ bias, float* __restrict__ C,
                   int K, int N,
                   const int* __restrict__ perm, const int* __restrict__ starts)
{
    int e = blockIdx.z;
    int seg_lo = 0, seg_hi = gridDim.y * BM;
    const float* Bp = Bw;
    const float* bp = bias;
    if (perm) {
        seg_lo = starts[e];
        seg_hi = starts[e + 1];
        Bp = Bw + (size_t)e * K * N;
        bp = bias + (size_t)e * N;
    }
    int m0 = blockIdx.y * BM;
    int n0 = blockIdx.x * BN;
    if (perm && (m0 >= seg_hi || m0 + BM <= seg_lo)) return;

    uint32_t sb = smem_u32(smem_dyn);
    int tid = threadIdx.x;

    // ---- cp.async source/dest precompute ----
    // A: 128 rows x 16k = 512 float4 chunks; 2 per thread
    int am_[2], ak4_[2];
    const float* agp[2];
    uint32_t asz[2];
#pragma unroll
    for (int i = 0; i < 2; i++) {
        int c = tid + i * 256;
        am_[i] = c >> 2;
        ak4_[i] = (c & 3) * 4;
        int grow = m0 + am_[i];
        bool ok = (!perm) || (grow >= seg_lo && grow < seg_hi);
        int src_row = perm ? (ok ? perm[grow] : 0) : grow;
        agp[i] = A + (size_t)src_row * K + ak4_[i];
        asz[i] = ok ? 16u : 0u;
    }
    // B: 16k x 256n = 1024 float4 chunks; 4 per thread
    int bkk[4], bn4[4];
#pragma unroll
    for (int i = 0; i < 4; i++) {
        int c = tid + i * 256;
        bkk[i] = c >> 6;
        bn4[i] = (c & 63) * 4;
    }
    const float* bbase = Bp + n0;

    // ---- warp/fragment identities ----
    int lane = tid & 31;
    int qr = lane >> 2;          // 0..7
    int qc = lane & 3;           // 0..3
    int wid = tid >> 5;
    int wm = wid >> 2;           // 0..1
    int wn = wid & 3;            // 0..3

    float acc[4][8][4];
#pragma unroll
    for (int i = 0; i < 4; i++)
#pragma unroll
        for (int j = 0; j < 8; j++)
#pragma unroll
            for (int c = 0; c < 4; c++) acc[i][j][c] = 0.f;

    int T = K / BK;

    // issue one stage's copies
    auto issue = [&](int t) {
        int s = t & (STAGES - 1);
        uint32_t ab = sb + (uint32_t)(s * AW) * 4u;
        uint32_t bb = sb + (uint32_t)(STAGES * AW + s * BW) * 4u;
        int k0 = t * BK;
#pragma unroll
        for (int i = 0; i < 2; i++)
            cp16(ab + (uint32_t)(am_[i] * ASTR + ak4_[i]) * 4u, agp[i] + k0, asz[i]);
#pragma unroll
        for (int i = 0; i < 4; i++)
            cp16(bb + (uint32_t)(bkk[i] * BSTR + bn4[i]) * 4u,
                 bbase + (size_t)(k0 + bkk[i]) * N + bn4[i], 16u);
        CP_COMMIT();
    };

    // prologue: stages 0..2
    issue(0);
    if (T > 1) issue(1);
    if (T > 2) issue(2);

    for (int t = 0; t < T; t++) {
        CP_WAIT2();
        __syncthreads();
        if (t + 3 < T) issue(t + 3);

        int s = t & (STAGES - 1);
        const float* As_ = smem_dyn + s * AW;
        const float* Bs_ = smem_dyn + STAGES * AW + s * BW;

#pragma unroll
        for (int ks = 0; ks < 2; ks++) {
            int k0s = ks * 8;
            uint32_t af[4][4];
            uint32_t bf[8][2];
#pragma unroll
            for (int mt = 0; mt < 4; mt++) {
                int mb = wm * 64 + mt * 16 + qr;
                af[mt][0] = f2tf32(As_[mb * ASTR + k0s + qc]);
                af[mt][1] = f2tf32(As_[(mb + 8) * ASTR + k0s + qc]);
                af[mt][2] = f2tf32(As_[mb * ASTR + k0s + qc + 4]);
                af[mt][3] = f2tf32(As_[(mb + 8) * ASTR + k0s + qc + 4]);
            }
#pragma unroll
            for (int nt = 0; nt < 8; nt++) {
                int nb = wn * 64 + nt * 8 + qr;
                bf[nt][0] = f2tf32(Bs_[(k0s + qc) * BSTR + nb]);
                bf[nt][1] = f2tf32(Bs_[(k0s + qc + 4) * BSTR + nb]);
            }
#pragma unroll
            for (int mt = 0; mt < 4; mt++)
#pragma unroll
                for (int nt = 0; nt < 8; nt++)
                    mma_tf32(acc[mt][nt], af[mt][0], af[mt][1], af[mt][2], af[mt][3],
                             bf[nt][0], bf[nt][1]);
        }
        __syncthreads();
    }

    // ---- epilogue: bias + relu; fragment: rows qr|qr+8, cols qc*2|+1 ----
#pragma unroll
    for (int nt = 0; nt < 8; nt++) {
        int col = n0 + wn * 64 + nt * 8 + qc * 2;
        float bv0 = bp[col];
        float bv1 = bp[col + 1];
#pragma unroll
        for (int mt = 0; mt < 4; mt++) {
            int row0 = m0 + wm * 64 + mt * 16 + qr;
            if (!perm || (row0 >= seg_lo && row0 < seg_hi)) {
                float2 o;
                o.x = fmaxf(acc[mt][nt][0] + bv0, 0.f);
                o.y = fmaxf(acc[mt][nt][1] + bv1, 0.f);
                *(float2*)(C + (size_t)row0 * N + col) = o;
            }
            int row1 = row0 + 8;
            if (!perm || (row1 >= seg_lo && row1 < seg_hi)) {
                float2 o;
                o.x = fmaxf(acc[mt][nt][2] + bv0, 0.f);
                o.y = fmaxf(acc[mt][nt][3] + bv1, 0.f);
                *(float2*)(C + (size_t)row1 * N + col) = o;
            }
        }
    }
}

// ---------------- x_dist = [hd0*hd1, hd1*hd2] ----------------
__global__ void xdist_kernel(const float* __restrict__ hd, float* __restrict__ xd)
{
    int i = blockIdx.x;
    const float* h = hd + (size_t)i * 3 * FC;
    float* xr = xd + (size_t)i * (2 * FC);
    for (int k = threadIdx.x; k < FC; k += blockDim.x) {
        float h0 = h[k];
        float h1 = h[FC + k];
        float h2 = h[2 * FC + k];
        xr[k] = h0 * h1;
        xr[FC + k] = h1 * h2;
    }
}

// ---------------- layer 2: out[orig] = h(1024) @ W2[e](1024,2) + b2[e] ----------------
__global__ void layer2_kernel(const float* __restrict__ h, const float* __restrict__ W2,
                              const float* __restrict__ b2,
                              const int* __restrict__ perm, const int* __restrict__ eid,
                              float* __restrict__ out, int out_row_base)
{
    int r = blockIdx.x;
    int orig = perm[r];
    int e = eid[orig];
    const float* hr = h + (size_t)r * FC;
    const float* w = W2 + (size_t)e * FC * 2;
    float s0 = 0.f, s1 = 0.f;
    for (int k = threadIdx.x; k < FC; k += blockDim.x) {
        float hv = hr[k];
        s0 = fmaf(hv, w[2 * k], s0);
        s1 = fmaf(hv, w[2 * k + 1], s1);
    }
#pragma unroll
    for (int o = 16; o; o >>= 1) {
        s0 += __shfl_down_sync(0xffffffffu, s0, o);
        s1 += __shfl_down_sync(0xffffffffu, s1, o);
    }
    __shared__ float sh0[8], sh1[8];
    int wid = threadIdx.x >> 5, lane = threadIdx.x & 31;
    if (lane == 0) { sh0[wid] = s0; sh1[wid] = s1; }
    __syncthreads();
    if (threadIdx.x == 0) {
        float t0 = b2[e * 2 + 0], t1 = b2[e * 2 + 1];
        int nw = blockDim.x >> 5;
        for (int i = 0; i < nw; i++) { t0 += sh0[i]; t1 += sh1[i]; }
        float* orow = out + (size_t)(out_row_base + orig) * 2;
        orow[0] = t0;
        orow[1] = t1;
    }
}

// ---------------- host ----------------
extern "C" void kernel_launch(void* const* d_in, const int* in_sizes, int n_in,
                              void* d_out, int out_size)
{
    const int n = NN;
    bool dictOrder = (in_sizes[3] == n);
    int wb = dictOrder ? 6 : 3;   // weight base index
    int eb = dictOrder ? 3 : 19;  // eid base index

    const float* rnn_feats = (const float*)d_in[0];
    const float* cube      = (const float*)d_in[1];
    const float* ego       = (const float*)d_in[2];
    const int* rnn_eid  = (const int*)d_in[eb + 0];
    const int* room_eid = (const int*)d_in[eb + 1];
    const int* dist_eid = (const int*)d_in[eb + 2];

    const float* Wc = (const float*)d_in[wb + 0];
    const float* bc = (const float*)d_in[wb + 1];
    const float* Wd = (const float*)d_in[wb + 2];
    const float* bd = (const float*)d_in[wb + 3];
    const float* W1_rnn  = (const float*)d_in[wb + 4];
    const float* b1_rnn  = (const float*)d_in[wb + 5];
    const float* W2_rnn  = (const float*)d_in[wb + 6];
    const float* b2_rnn  = (const float*)d_in[wb + 7];
    const float* W1_room = (const float*)d_in[wb + 8];
    const float* b1_room = (const float*)d_in[wb + 9];
    const float* W2_room = (const float*)d_in[wb + 10];
    const float* b2_room = (const float*)d_in[wb + 11];
    const float* W1_dist = (const float*)d_in[wb + 12];
    const float* b1_dist = (const float*)d_in[wb + 13];
    const float* W2_dist = (const float*)d_in[wb + 14];
    const float* b2_dist = (const float*)d_in[wb + 15];

    float* out = (float*)d_out;

    float *hc, *hd, *xd, *h_rnn, *h_room, *h_dist;
    int *perm_rnn, *perm_room, *perm_dist, *st_rnn, *st_room, *st_dist;
    cudaGetSymbolAddress((void**)&hc, g_hc);
    cudaGetSymbolAddress((void**)&hd, g_hd);
    cudaGetSymbolAddress((void**)&xd, g_xd);
    cudaGetSymbolAddress((void**)&h_rnn, g_h_rnn);
    cudaGetSymbolAddress((void**)&h_room, g_h_room);
    cudaGetSymbolAddress((void**)&h_dist, g_h_dist);
    cudaGetSymbolAddress((void**)&perm_rnn, g_perm_rnn);
    cudaGetSymbolAddress((void**)&perm_room, g_perm_room);
    cudaGetSymbolAddress((void**)&perm_dist, g_perm_dist);
    cudaGetSymbolAddress((void**)&st_rnn, g_starts_rnn);
    cudaGetSymbolAddress((void**)&st_room, g_starts_room);
    cudaGetSymbolAddress((void**)&st_dist, g_starts_dist);

    static bool attr_set = false;
    if (!attr_set) {
        cudaFuncSetAttribute(tf32gemm_bias_relu,
                             cudaFuncAttributeMaxDynamicSharedMemorySize, SMEM_BYTES);
        attr_set = true;
    }

    // 1) routing
    route_kernel<<<1, 256>>>(rnn_eid, n, 3, perm_rnn, st_rnn);
    route_kernel<<<1, 256>>>(room_eid, n, 2, perm_room, st_room);
    route_kernel<<<1, 256>>>(dist_eid, n, 2, perm_dist, st_dist);

    // 2) shared front-end GEMMs
    {
        dim3 g(FC / BN, 16384 / BM, 1);
        tf32gemm_bias_relu<<<g, 256, SMEM_BYTES>>>(cube, Wc, bc, hc, CUBE_K, FC, nullptr, nullptr);
    }
    {
        dim3 g(FC / BN, 6144 / BM, 1);
        tf32gemm_bias_relu<<<g, 256, SMEM_BYTES>>>(ego, Wd, bd, hd, EGO_K, FC, nullptr, nullptr);
    }

    // 3) x_dist elementwise
    xdist_kernel<<<n, 256>>>(hd, xd);

    // 4) routed layer-1 GEMMs
    {
        dim3 g(FC / BN, n / BM, 3);
        tf32gemm_bias_relu<<<g, 256, SMEM_BYTES>>>(rnn_feats, W1_rnn, b1_rnn, h_rnn, RNN2_K, FC, perm_rnn, st_rnn);
    }
    {
        dim3 g(FC / BN, n / BM, 2);
        tf32gemm_bias_relu<<<g, 256, SMEM_BYTES>>>(hc, W1_room, b1_room, h_room, ROOM_K, FC, perm_room, st_room);
    }
    {
        dim3 g(FC / BN, n / BM, 2);
        tf32gemm_bias_relu<<<g, 256, SMEM_BYTES>>>(xd, W1_dist, b1_dist, h_dist, DIST_K, FC, perm_dist, st_dist);
    }

    // 5) layer 2 + scatter
    layer2_kernel<<<n, 256>>>(h_rnn, W2_rnn, b2_rnn, perm_rnn, rnn_eid, out, 0);
    layer2_kernel<<<n, 256>>>(h_room, W2_room, b2_room, perm_room, room_eid, out, n);
    layer2_kernel<<<n, 256>>>(h_dist, W2_dist, b2_dist, perm_dist, dist_eid, out, 2 * n);
}

// round 15
// speedup vs baseline: 1.0020x; 1.0020x over previous
#include <cuda_runtime.h>
#include <cuda_bf16.h>
#include <cstdint>

// Problem constants
#define NN     2048
#define FC     1024
#define CUBE_K 3200
#define EGO_K  3712   // EGO + RNN
#define RNN2_K 1024   // 2*RNN
#define ROOM_K 8192   // 8*FC
#define DIST_K 2048   // 2*FC

// ---------------- scratch (device globals; no allocation) ----------------
__device__ float g_hc[16384 * 1024];
__device__ float g_hd[6144 * 1024];
__device__ float g_xd[2048 * 2048];
__device__ float g_h_rnn[2048 * 1024];
__device__ float g_h_room[2048 * 1024];
__device__ float g_h_dist[2048 * 1024];
__device__ int   g_perm_rnn[NN];
__device__ int   g_perm_room[NN];
__device__ int   g_perm_dist[NN];
__device__ int   g_starts_rnn[8];
__device__ int   g_starts_room[8];
__device__ int   g_starts_dist[8];

// ---------------- routing: counting sort in one block ----------------
__global__ void route_kernel(const int* __restrict__ eid, int n, int E,
                             int* __restrict__ perm, int* __restrict__ starts)
{
    __shared__ int cnt[4];
    __shared__ int off[4];
    int tid = threadIdx.x;
    if (tid < 4) cnt[tid] = 0;
    __syncthreads();
    for (int i = tid; i < n; i += blockDim.x)
        atomicAdd(&cnt[eid[i]], 1);
    __syncthreads();
    if (tid == 0) {
        int s = 0;
        for (int e = 0; e < E; e++) { off[e] = s; starts[e] = s; s += cnt[e]; }
        starts[E] = s;
    }
    __syncthreads();
    for (int i = tid; i < n; i += blockDim.x) {
        int pos = atomicAdd(&off[eid[i]], 1);
        perm[pos] = i;
    }
}

// ---------------- helpers ----------------
__device__ __forceinline__ uint32_t smem_u32(const void* p) {
    uint32_t a;
    asm("{ .reg .u64 t; cvta.to.shared.u64 t, %1; cvt.u32.u64 %0, t; }" : "=r"(a) : "l"(p));
    return a;
}

__device__ __forceinline__ uint32_t f2tf32(float x) {
    uint32_t r;
    asm("cvt.rna.tf32.f32 %0, %1;" : "=r"(r) : "f"(x));
    return r;
}

__device__ __forceinline__ void cp16(uint32_t dst, const void* src, uint32_t srcsize) {
    asm volatile("cp.async.ca.shared.global [%0], [%1], 16, %2;"
                 :: "r"(dst), "l"(src), "r"(srcsize) : "memory");
}
#define CP_COMMIT() asm volatile("cp.async.commit_group;" ::: "memory")
#define CP_WAIT2()  asm volatile("cp.async.wait_group 2;" ::: "memory")

__device__ __forceinline__ void mma_tf32(float c[4], uint32_t a0, uint32_t a1,
                                         uint32_t a2, uint32_t a3,
                                         uint32_t b0, uint32_t b1)
{
    asm volatile(
        "mma.sync.aligned.m16n8k8.row.col.f32.tf32.tf32.f32 "
        "{%0,%1,%2,%3}, {%4,%5,%6,%7}, {%8,%9}, {%0,%1,%2,%3};"
        : "+f"(c[0]), "+f"(c[1]), "+f"(c[2]), "+f"(c[3])
        : "r"(a0), "r"(a1), "r"(a2), "r"(a3), "r"(b0), "r"(b1));
}

// ---------------- tf32 tensor-core GEMM with cp.async pipeline ----------------
// CTA tile 128x256, BK=16, 4-stage cp.async pipeline, 256 threads = 8 warps
// (2 M x 4 N), warp tile 64x64 (4 m-tiles x 8 n-tiles of m16n8k8).
// A smem: [m][k] stride 20 (bank-perfect for fragment loads).
// B smem: [k][n] stride 264.
#define BM 128
#define BN 256
#define BK 16
#define ASTR 20
#define BSTR 264
#define STAGES 4
#define AW (BM * ASTR)            // words per A stage = 2560
#define BW (BK * BSTR)            // words per B stage = 4224
#define SMEM_BYTES ((AW + BW) * STAGES * 4)   // 108544

extern __shared__ float smem_dyn[];

__global__ void __launch_bounds__(256)
tf32gemm_bias_relu(const float* __restrict__ A, const float* __restrict__ Bw,
                   const float* __restrict__ bias, float* __restrict__ C,
                   int K, int N,
                   const int* __restrict__ perm, const int* __restrict__ starts)
{
    int e = blockIdx.z;
    int seg_lo = 0, seg_hi = gridDim.y * BM;
    const float* Bp = Bw;
    const float* bp = bias;
    if (perm) {
        seg_lo = starts[e];
        seg_hi = starts[e + 1];
        Bp = Bw + (size_t)e * K * N;
        bp = bias + (size_t)e * N;
    }
    int m0 = blockIdx.y * BM;
    int n0 = blockIdx.x * BN;
    if (perm && (m0 >= seg_hi || m0 + BM <= seg_lo)) return;

    uint32_t sb = smem_u32(smem_dyn);
    int tid = threadIdx.x;

    // ---- cp.async source/dest precompute ----
    // A: 128 rows x 16k = 512 float4 chunks; 2 per thread
    int am_[2], ak4_[2];
    const float* agp[2];
    uint32_t asz[2];
#pragma unroll
    for (int i = 0; i < 2; i++) {
        int c = tid + i * 256;
        am_[i] = c >> 2;
        ak4_[i] = (c & 3) * 4;
        int grow = m0 + am_[i];
        bool ok = (!perm) || (grow >= seg_lo && grow < seg_hi);
        int src_row = perm ? (ok ? perm[grow] : 0) : grow;
        agp[i] = A + (size_t)src_row * K + ak4_[i];
        asz[i] = ok ? 16u : 0u;
    }
    // B: 16k x 256n = 1024 float4 chunks; 4 per thread
    int bkk[4], bn4[4];
#pragma unroll
    for (int i = 0; i < 4; i++) {
        int c = tid + i * 256;
        bkk[i] = c >> 6;
        bn4[i] = (c & 63) * 4;
    }
    const float* bbase = Bp + n0;

    // ---- warp/fragment identities ----
    int lane = tid & 31;
    int qr = lane >> 2;          // 0..7
    int qc = lane & 3;           // 0..3
    int wid = tid >> 5;
    int wm = wid >> 2;           // 0..1
    int wn = wid & 3;            // 0..3

    float acc[4][8][4];
#pragma unroll
    for (int i = 0; i < 4; i++)
#pragma unroll
        for (int j = 0; j < 8; j++)
#pragma unroll
            for (int c = 0; c < 4; c++) acc[i][j][c] = 0.f;

    int T = K / BK;

    // issue one stage's copies
    auto issue = [&](int t) {
        int s = t & (STAGES - 1);
        uint32_t ab = sb + (uint32_t)(s * AW) * 4u;
        uint32_t bb = sb + (uint32_t)(STAGES * AW + s * BW) * 4u;
        int k0 = t * BK;
#pragma unroll
        for (int i = 0; i < 2; i++)
            cp16(ab + (uint32_t)(am_[i] * ASTR + ak4_[i]) * 4u, agp[i] + k0, asz[i]);
#pragma unroll
        for (int i = 0; i < 4; i++)
            cp16(bb + (uint32_t)(bkk[i] * BSTR + bn4[i]) * 4u,
                 bbase + (size_t)(k0 + bkk[i]) * N + bn4[i], 16u);
        CP_COMMIT();
    };

    // prologue: stages 0..2
    issue(0);
    if (T > 1) issue(1);
    if (T > 2) issue(2);

    for (int t = 0; t < T; t++) {
        CP_WAIT2();
        __syncthreads();
        if (t + 3 < T) issue(t + 3);

        int s = t & (STAGES - 1);
        const float* As_ = smem_dyn + s * AW;
        const float* Bs_ = smem_dyn + STAGES * AW + s * BW;

#pragma unroll
        for (int ks = 0; ks < 2; ks++) {
            int k0s = ks * 8;
            uint32_t af[4][4];
            uint32_t bf[8][2];
#pragma unroll
            for (int mt = 0; mt < 4; mt++) {
                int mb = wm * 64 + mt * 16 + qr;
                af[mt][0] = f2tf32(As_[mb * ASTR + k0s + qc]);
                af[mt][1] = f2tf32(As_[(mb + 8) * ASTR + k0s + qc]);
                af[mt][2] = f2tf32(As_[mb * ASTR + k0s + qc + 4]);
                af[mt][3] = f2tf32(As_[(mb + 8) * ASTR + k0s + qc + 4]);
            }
#pragma unroll
            for (int nt = 0; nt < 8; nt++) {
                int nb = wn * 64 + nt * 8 + qr;
                bf[nt][0] = f2tf32(Bs_[(k0s + qc) * BSTR + nb]);
                bf[nt][1] = f2tf32(Bs_[(k0s + qc + 4) * BSTR + nb]);
            }
#pragma unroll
            for (int mt = 0; mt < 4; mt++)
#pragma unroll
                for (int nt = 0; nt < 8; nt++)
                    mma_tf32(acc[mt][nt], af[mt][0], af[mt][1], af[mt][2], af[mt][3],
                             bf[nt][0], bf[nt][1]);
        }
        __syncthreads();
    }

    // ---- epilogue: bias + relu; fragment: rows qr|qr+8, cols qc*2|+1 ----
#pragma unroll
    for (int nt = 0; nt < 8; nt++) {
        int col = n0 + wn * 64 + nt * 8 + qc * 2;
        float bv0 = bp[col];
        float bv1 = bp[col + 1];
#pragma unroll
        for (int mt = 0; mt < 4; mt++) {
            int row0 = m0 + wm * 64 + mt * 16 + qr;
            if (!perm || (row0 >= seg_lo && row0 < seg_hi)) {
                float2 o;
                o.x = fmaxf(acc[mt][nt][0] + bv0, 0.f);
                o.y = fmaxf(acc[mt][nt][1] + bv1, 0.f);
                *(float2*)(C + (size_t)row0 * N + col) = o;
            }
            int row1 = row0 + 8;
            if (!perm || (row1 >= seg_lo && row1 < seg_hi)) {
                float2 o;
                o.x = fmaxf(acc[mt][nt][2] + bv0, 0.f);
                o.y = fmaxf(acc[mt][nt][3] + bv1, 0.f);
                *(float2*)(C + (size_t)row1 * N + col) = o;
            }
        }
    }
}

// ---------------- x_dist = [hd0*hd1, hd1*hd2] ----------------
__global__ void xdist_kernel(const float* __restrict__ hd, float* __restrict__ xd)
{
    int i = blockIdx.x;
    const float* h = hd + (size_t)i * 3 * FC;
    float* xr = xd + (size_t)i * (2 * FC);
    for (int k = threadIdx.x; k < FC; k += blockDim.x) {
        float h0 = h[k];
        float h1 = h[FC + k];
        float h2 = h[2 * FC + k];
        xr[k] = h0 * h1;
        xr[FC + k] = h1 * h2;
    }
}

// ---------------- layer 2: out[orig] = h(1024) @ W2[e](1024,2) + b2[e] ----------------
__global__ void layer2_kernel(const float* __restrict__ h, const float* __restrict__ W2,
                              const float* __restrict__ b2,
                              const int* __restrict__ perm, const int* __restrict__ eid,
                              float* __restrict__ out, int out_row_base)
{
    int r = blockIdx.x;
    int orig = perm[r];
    int e = eid[orig];
    const float* hr = h + (size_t)r * FC;
    const float* w = W2 + (size_t)e * FC * 2;
    float s0 = 0.f, s1 = 0.f;
    for (int k = threadIdx.x; k < FC; k += blockDim.x) {
        float hv = hr[k];
        s0 = fmaf(hv, w[2 * k], s0);
        s1 = fmaf(hv, w[2 * k + 1], s1);
    }
#pragma unroll
    for (int o = 16; o; o >>= 1) {
        s0 += __shfl_down_sync(0xffffffffu, s0, o);
        s1 += __shfl_down_sync(0xffffffffu, s1, o);
    }
    __shared__ float sh0[8], sh1[8];
    int wid = threadIdx.x >> 5, lane = threadIdx.x & 31;
    if (lane == 0) { sh0[wid] = s0; sh1[wid] = s1; }
    __syncthreads();
    if (threadIdx.x == 0) {
        float t0 = b2[e * 2 + 0], t1 = b2[e * 2 + 1];
        int nw = blockDim.x >> 5;
        for (int i = 0; i < nw; i++) { t0 += sh0[i]; t1 += sh1[i]; }
        float* orow = out + (size_t)(out_row_base + orig) * 2;
        orow[0] = t0;
        orow[1] = t1;
    }
}

// ---------------- host ----------------
extern "C" void kernel_launch(void* const* d_in, const int* in_sizes, int n_in,
                              void* d_out, int out_size)
{
    const int n = NN;
    bool dictOrder = (in_sizes[3] == n);
    int wb = dictOrder ? 6 : 3;   // weight base index
    int eb = dictOrder ? 3 : 19;  // eid base index

    const float* rnn_feats = (const float*)d_in[0];
    const float* cube      = (const float*)d_in[1];
    const float* ego       = (const float*)d_in[2];
    const int* rnn_eid  = (const int*)d_in[eb + 0];
    const int* room_eid = (const int*)d_in[eb + 1];
    const int* dist_eid = (const int*)d_in[eb + 2];

    const float* Wc = (const float*)d_in[wb + 0];
    const float* bc = (const float*)d_in[wb + 1];
    const float* Wd = (const float*)d_in[wb + 2];
    const float* bd = (const float*)d_in[wb + 3];
    const float* W1_rnn  = (const float*)d_in[wb + 4];
    const float* b1_rnn  = (const float*)d_in[wb + 5];
    const float* W2_rnn  = (const float*)d_in[wb + 6];
    const float* b2_rnn  = (const float*)d_in[wb + 7];
    const float* W1_room = (const float*)d_in[wb + 8];
    const float* b1_room = (const float*)d_in[wb + 9];
    const float* W2_room = (const float*)d_in[wb + 10];
    const float* b2_room = (const float*)d_in[wb + 11];
    const float* W1_dist = (const float*)d_in[wb + 12];
    const float* b1_dist = (const float*)d_in[wb + 13];
    const float* W2_dist = (const float*)d_in[wb + 14];
    const float* b2_dist = (const float*)d_in[wb + 15];

    float* out = (float*)d_out;

    float *hc, *hd, *xd, *h_rnn, *h_room, *h_dist;
    int *perm_rnn, *perm_room, *perm_dist, *st_rnn, *st_room, *st_dist;
    cudaGetSymbolAddress((void**)&hc, g_hc);
    cudaGetSymbolAddress((void**)&hd, g_hd);
    cudaGetSymbolAddress((void**)&xd, g_xd);
    cudaGetSymbolAddress((void**)&h_rnn, g_h_rnn);
    cudaGetSymbolAddress((void**)&h_room, g_h_room);
    cudaGetSymbolAddress((void**)&h_dist, g_h_dist);
    cudaGetSymbolAddress((void**)&perm_rnn, g_perm_rnn);
    cudaGetSymbolAddress((void**)&perm_room, g_perm_room);
    cudaGetSymbolAddress((void**)&perm_dist, g_perm_dist);
    cudaGetSymbolAddress((void**)&st_rnn, g_starts_rnn);
    cudaGetSymbolAddress((void**)&st_room, g_starts_room);
    cudaGetSymbolAddress((void**)&st_dist, g_starts_dist);

    static bool attr_set = false;
    if (!attr_set) {
        cudaFuncSetAttribute(tf32gemm_bias_relu,
                             cudaFuncAttributeMaxDynamicSharedMemorySize, SMEM_BYTES);
        attr_set = true;
    }

    // 1) routing
    route_kernel<<<1, 256>>>(rnn_eid, n, 3, perm_rnn, st_rnn);
    route_kernel<<<1, 256>>>(room_eid, n, 2, perm_room, st_room);
    route_kernel<<<1, 256>>>(dist_eid, n, 2, perm_dist, st_dist);

    // 2) shared front-end GEMMs
    {
        dim3 g(FC / BN, 16384 / BM, 1);
        tf32gemm_bias_relu<<<g, 256, SMEM_BYTES>>>(cube, Wc, bc, hc, CUBE_K, FC, nullptr, nullptr);
    }
    {
        dim3 g(FC / BN, 6144 / BM, 1);
        tf32gemm_bias_relu<<<g, 256, SMEM_BYTES>>>(ego, Wd, bd, hd, EGO_K, FC, nullptr, nullptr);
    }

    // 3) x_dist elementwise
    xdist_kernel<<<n, 256>>>(hd, xd);

    // 4) routed layer-1 GEMMs
    {
        dim3 g(FC / BN, n / BM, 3);
        tf32gemm_bias_relu<<<g, 256, SMEM_BYTES>>>(rnn_feats, W1_rnn, b1_rnn, h_rnn, RNN2_K, FC, perm_rnn, st_rnn);
    }
    {
        dim3 g(FC / BN, n / BM, 2);
        tf32gemm_bias_relu<<<g, 256, SMEM_BYTES>>>(hc, W1_room, b1_room, h_room, ROOM_K, FC, perm_room, st_room);
    }
    {
        dim3 g(FC / BN, n / BM, 2);
        tf32gemm_bias_relu<<<g, 256, SMEM_BYTES>>>(xd, W1_dist, b1_dist, h_dist, DIST_K, FC, perm_dist, st_dist);
    }

    // 5) layer 2 + scatter
    layer2_kernel<<<n, 256>>>(h_rnn, W2_rnn, b2_rnn, perm_rnn, rnn_eid, out, 0);
    layer2_kernel<<<n, 256>>>(h_room, W2_room, b2_room, perm_room, room_eid, out, n);
    layer2_kernel<<<n, 256>>>(h_dist, W2_dist, b2_dist, perm_dist, dist_eid, out, 2 * n);
}

// round 16
// speedup vs baseline: 1.0021x; 1.0000x over previous
#include <cuda_runtime.h>
#include <cuda_bf16.h>
#include <cstdint>

// Problem constants
#define NN     2048
#define FC     1024
#define CUBE_K 3200
#define EGO_K  3712   // EGO + RNN
#define RNN2_K 1024   // 2*RNN
#define ROOM_K 8192   // 8*FC
#define DIST_K 2048   // 2*FC

// ---------------- scratch (device globals; no allocation) ----------------
__device__ float g_hc[16384 * 1024];
__device__ float g_hd[6144 * 1024];
__device__ float g_xd[2048 * 2048];
__device__ float g_h_rnn[2048 * 1024];
__device__ float g_h_room[2048 * 1024];
__device__ float g_h_dist[2048 * 1024];
__device__ int   g_perm_rnn[NN];
__device__ int   g_perm_room[NN];
__device__ int   g_perm_dist[NN];
__device__ int   g_starts_rnn[8];
__device__ int   g_starts_room[8];
__device__ int   g_starts_dist[8];

// ---------------- routing: counting sort in one block ----------------
__global__ void route_kernel(const int* __restrict__ eid, int n, int E,
                             int* __restrict__ perm, int* __restrict__ starts)
{
    __shared__ int cnt[4];
    __shared__ int off[4];
    int tid = threadIdx.x;
    if (tid < 4) cnt[tid] = 0;
    __syncthreads();
    for (int i = tid; i < n; i += blockDim.x)
        atomicAdd(&cnt[eid[i]], 1);
    __syncthreads();
    if (tid == 0) {
        int s = 0;
        for (int e = 0; e < E; e++) { off[e] = s; starts[e] = s; s += cnt[e]; }
        starts[E] = s;
    }
    __syncthreads();
    for (int i = tid; i < n; i += blockDim.x) {
        int pos = atomicAdd(&off[eid[i]], 1);
        perm[pos] = i;
    }
}

// ---------------- helpers ----------------
__device__ __forceinline__ uint32_t smem_u32(const void* p) {
    uint32_t a;
    asm("{ .reg .u64 t; cvta.to.shared.u64 t, %1; cvt.u32.u64 %0, t; }" : "=r"(a) : "l"(p));
    return a;
}

__device__ __forceinline__ uint32_t f2tf32(float x) {
    uint32_t r;
    asm("cvt.rna.tf32.f32 %0, %1;" : "=r"(r) : "f"(x));
    return r;
}

__device__ __forceinline__ void cp16(uint32_t dst, const void* src, uint32_t srcsize) {
    asm volatile("cp.async.ca.shared.global [%0], [%1], 16, %2;"
                 :: "r"(dst), "l"(src), "r"(srcsize) : "memory");
}
#define CP_COMMIT() asm volatile("cp.async.commit_group;" ::: "memory")
#define CP_WAIT2()  asm volatile("cp.async.wait_group 2;" ::: "memory")

__device__ __forceinline__ void mma_tf32(float c[4], uint32_t a0, uint32_t a1,
                                         uint32_t a2, uint32_t a3,
                                         uint32_t b0, uint32_t b1)
{
    asm volatile(
        "mma.sync.aligned.m16n8k8.row.col.f32.tf32.tf32.f32 "
        "{%0,%1,%2,%3}, {%4,%5,%6,%7}, {%8,%9}, {%0,%1,%2,%3};"
        : "+f"(c[0]), "+f"(c[1]), "+f"(c[2]), "+f"(c[3])
        : "r"(a0), "r"(a1), "r"(a2), "r"(a3), "r"(b0), "r"(b1));
}

// ---------------- tf32 tensor-core GEMM with cp.async pipeline ----------------
// CTA tile 128x256, BK=16, 4-stage cp.async pipeline, 256 threads = 8 warps
// (2 M x 4 N), warp tile 64x64 (4 m-tiles x 8 n-tiles of m16n8k8).
// A smem: [m][k] stride 20 (bank-perfect for fragment loads).
// B smem: [k][n] stride 264.
#define BM 128
#define BN 256
#define BK 16
#define ASTR 20
#define BSTR 264
#define STAGES 4
#define AW (BM * ASTR)            // words per A stage = 2560
#define BW (BK * BSTR)            // words per B stage = 4224
#define SMEM_BYTES ((AW + BW) * STAGES * 4)   // 108544

extern __shared__ float smem_dyn[];

__global__ void __launch_bounds__(256)
tf32gemm_bias_relu(const float* __restrict__ A, const float* __restrict__ Bw,
                   const float* __restrict__ bias, float* __restrict__ C,
                   int K, int N,
                   const int* __restrict__ perm, const int* __restrict__ starts)
{
    int e = blockIdx.z;
    int seg_lo = 0, seg_hi = gridDim.y * BM;
    const float* Bp = Bw;
    const float* bp = bias;
    if (perm) {
        seg_lo = starts[e];
        seg_hi = starts[e + 1];
        Bp = Bw + (size_t)e * K * N;
        bp = bias + (size_t)e * N;
    }
    int m0 = blockIdx.y * BM;
    int n0 = blockIdx.x * BN;
    if (perm && (m0 >= seg_hi || m0 + BM <= seg_lo)) return;

    uint32_t sb = smem_u32(smem_dyn);
    int tid = threadIdx.x;

    // ---- cp.async source/dest precompute ----
    // A: 128 rows x 16k = 512 float4 chunks; 2 per thread
    int am_[2], ak4_[2];
    const float* agp[2];
    uint32_t asz[2];
#pragma unroll
    for (int i = 0; i < 2; i++) {
        int c = tid + i * 256;
        am_[i] = c >> 2;
        ak4_[i] = (c & 3) * 4;
        int grow = m0 + am_[i];
        bool ok = (!perm) || (grow >= seg_lo && grow < seg_hi);
        int src_row = perm ? (ok ? perm[grow] : 0) : grow;
        agp[i] = A + (size_t)src_row * K + ak4_[i];
        asz[i] = ok ? 16u : 0u;
    }
    // B: 16k x 256n = 1024 float4 chunks; 4 per thread
    int bkk[4], bn4[4];
#pragma unroll
    for (int i = 0; i < 4; i++) {
        int c = tid + i * 256;
        bkk[i] = c >> 6;
        bn4[i] = (c & 63) * 4;
    }
    const float* bbase = Bp + n0;

    // ---- warp/fragment identities ----
    int lane = tid & 31;
    int qr = lane >> 2;          // 0..7
    int qc = lane & 3;           // 0..3
    int wid = tid >> 5;
    int wm = wid >> 2;           // 0..1
    int wn = wid & 3;            // 0..3

    float acc[4][8][4];
#pragma unroll
    for (int i = 0; i < 4; i++)
#pragma unroll
        for (int j = 0; j < 8; j++)
#pragma unroll
            for (int c = 0; c < 4; c++) acc[i][j][c] = 0.f;

    int T = K / BK;

    // issue one stage's copies
    auto issue = [&](int t) {
        int s = t & (STAGES - 1);
        uint32_t ab = sb + (uint32_t)(s * AW) * 4u;
        uint32_t bb = sb + (uint32_t)(STAGES * AW + s * BW) * 4u;
        int k0 = t * BK;
#pragma unroll
        for (int i = 0; i < 2; i++)
            cp16(ab + (uint32_t)(am_[i] * ASTR + ak4_[i]) * 4u, agp[i] + k0, asz[i]);
#pragma unroll
        for (int i = 0; i < 4; i++)
            cp16(bb + (uint32_t)(bkk[i] * BSTR + bn4[i]) * 4u,
                 bbase + (size_t)(k0 + bkk[i]) * N + bn4[i], 16u);
        CP_COMMIT();
    };

    // prologue: stages 0..2
    issue(0);
    if (T > 1) issue(1);
    if (T > 2) issue(2);

    for (int t = 0; t < T; t++) {
        CP_WAIT2();
        __syncthreads();
        if (t + 3 < T) issue(t + 3);

        int s = t & (STAGES - 1);
        const float* As_ = smem_dyn + s * AW;
        const float* Bs_ = smem_dyn + STAGES * AW + s * BW;

#pragma unroll
        for (int ks = 0; ks < 2; ks++) {
            int k0s = ks * 8;
            uint32_t af[4][4];
            uint32_t bf[8][2];
#pragma unroll
            for (int mt = 0; mt < 4; mt++) {
                int mb = wm * 64 + mt * 16 + qr;
                af[mt][0] = f2tf32(As_[mb * ASTR + k0s + qc]);
                af[mt][1] = f2tf32(As_[(mb + 8) * ASTR + k0s + qc]);
                af[mt][2] = f2tf32(As_[mb * ASTR + k0s + qc + 4]);
                af[mt][3] = f2tf32(As_[(mb + 8) * ASTR + k0s + qc + 4]);
            }
#pragma unroll
            for (int nt = 0; nt < 8; nt++) {
                int nb = wn * 64 + nt * 8 + qr;
                bf[nt][0] = f2tf32(Bs_[(k0s + qc) * BSTR + nb]);
                bf[nt][1] = f2tf32(Bs_[(k0s + qc + 4) * BSTR + nb]);
            }
#pragma unroll
            for (int mt = 0; mt < 4; mt++)
#pragma unroll
                for (int nt = 0; nt < 8; nt++)
                    mma_tf32(acc[mt][nt], af[mt][0], af[mt][1], af[mt][2], af[mt][3],
                             bf[nt][0], bf[nt][1]);
        }
        __syncthreads();
    }

    // ---- epilogue: bias + relu; fragment: rows qr|qr+8, cols qc*2|+1 ----
#pragma unroll
    for (int nt = 0; nt < 8; nt++) {
        int col = n0 + wn * 64 + nt * 8 + qc * 2;
        float bv0 = bp[col];
        float bv1 = bp[col + 1];
#pragma unroll
        for (int mt = 0; mt < 4; mt++) {
            int row0 = m0 + wm * 64 + mt * 16 + qr;
            if (!perm || (row0 >= seg_lo && row0 < seg_hi)) {
                float2 o;
                o.x = fmaxf(acc[mt][nt][0] + bv0, 0.f);
                o.y = fmaxf(acc[mt][nt][1] + bv1, 0.f);
                *(float2*)(C + (size_t)row0 * N + col) = o;
            }
            int row1 = row0 + 8;
            if (!perm || (row1 >= seg_lo && row1 < seg_hi)) {
                float2 o;
                o.x = fmaxf(acc[mt][nt][2] + bv0, 0.f);
                o.y = fmaxf(acc[mt][nt][3] + bv1, 0.f);
                *(float2*)(C + (size_t)row1 * N + col) = o;
            }
        }
    }
}

// ---------------- x_dist = [hd0*hd1, hd1*hd2] ----------------
__global__ void xdist_kernel(const float* __restrict__ hd, float* __restrict__ xd)
{
    int i = blockIdx.x;
    const float* h = hd + (size_t)i * 3 * FC;
    float* xr = xd + (size_t)i * (2 * FC);
    for (int k = threadIdx.x; k < FC; k += blockDim.x) {
        float h0 = h[k];
        float h1 = h[FC + k];
        float h2 = h[2 * FC + k];
        xr[k] = h0 * h1;
        xr[FC + k] = h1 * h2;
    }
}

// ---------------- layer 2: out[orig] = h(1024) @ W2[e](1024,2) + b2[e] ----------------
__global__ void layer2_kernel(const float* __restrict__ h, const float* __restrict__ W2,
                              const float* __restrict__ b2,
                              const int* __restrict__ perm, const int* __restrict__ eid,
                              float* __restrict__ out, int out_row_base)
{
    int r = blockIdx.x;
    int orig = perm[r];
    int e = eid[orig];
    const float* hr = h + (size_t)r * FC;
    const float* w = W2 + (size_t)e * FC * 2;
    float s0 = 0.f, s1 = 0.f;
    for (int k = threadIdx.x; k < FC; k += blockDim.x) {
        float hv = hr[k];
        s0 = fmaf(hv, w[2 * k], s0);
        s1 = fmaf(hv, w[2 * k + 1], s1);
    }
#pragma unroll
    for (int o = 16; o; o >>= 1) {
        s0 += __shfl_down_sync(0xffffffffu, s0, o);
        s1 += __shfl_down_sync(0xffffffffu, s1, o);
    }
    __shared__ float sh0[8], sh1[8];
    int wid = threadIdx.x >> 5, lane = threadIdx.x & 31;
    if (lane == 0) { sh0[wid] = s0; sh1[wid] = s1; }
    __syncthreads();
    if (threadIdx.x == 0) {
        float t0 = b2[e * 2 + 0], t1 = b2[e * 2 + 1];
        int nw = blockDim.x >> 5;
        for (int i = 0; i < nw; i++) { t0 += sh0[i]; t1 += sh1[i]; }
        float* orow = out + (size_t)(out_row_base + orig) * 2;
        orow[0] = t0;
        orow[1] = t1;
    }
}

// ---------------- host ----------------
extern "C" void kernel_launch(void* const* d_in, const int* in_sizes, int n_in,
                              void* d_out, int out_size)
{
    const int n = NN;
    bool dictOrder = (in_sizes[3] == n);
    int wb = dictOrder ? 6 : 3;   // weight base index
    int eb = dictOrder ? 3 : 19;  // eid base index

    const float* rnn_feats = (const float*)d_in[0];
    const float* cube      = (const float*)d_in[1];
    const float* ego       = (const float*)d_in[2];
    const int* rnn_eid  = (const int*)d_in[eb + 0];
    const int* room_eid = (const int*)d_in[eb + 1];
    const int* dist_eid = (const int*)d_in[eb + 2];

    const float* Wc = (const float*)d_in[wb + 0];
    const float* bc = (const float*)d_in[wb + 1];
    const float* Wd = (const float*)d_in[wb + 2];
    const float* bd = (const float*)d_in[wb + 3];
    const float* W1_rnn  = (const float*)d_in[wb + 4];
    const float* b1_rnn  = (const float*)d_in[wb + 5];
    const float* W2_rnn  = (const float*)d_in[wb + 6];
    const float* b2_rnn  = (const float*)d_in[wb + 7];
    const float* W1_room = (const float*)d_in[wb + 8];
    const float* b1_room = (const float*)d_in[wb + 9];
    const float* W2_room = (const float*)d_in[wb + 10];
    const float* b2_room = (const float*)d_in[wb + 11];
    const float* W1_dist = (const float*)d_in[wb + 12];
    const float* b1_dist = (const float*)d_in[wb + 13];
    const float* W2_dist = (const float*)d_in[wb + 14];
    const float* b2_dist = (const float*)d_in[wb + 15];

    float* out = (float*)d_out;

    float *hc, *hd, *xd, *h_rnn, *h_room, *h_dist;
    int *perm_rnn, *perm_room, *perm_dist, *st_rnn, *st_room, *st_dist;
    cudaGetSymbolAddress((void**)&hc, g_hc);
    cudaGetSymbolAddress((void**)&hd, g_hd);
    cudaGetSymbolAddress((void**)&xd, g_xd);
    cudaGetSymbolAddress((void**)&h_rnn, g_h_rnn);
    cudaGetSymbolAddress((void**)&h_room, g_h_room);
    cudaGetSymbolAddress((void**)&h_dist, g_h_dist);
    cudaGetSymbolAddress((void**)&perm_rnn, g_perm_rnn);
    cudaGetSymbolAddress((void**)&perm_room, g_perm_room);
    cudaGetSymbolAddress((void**)&perm_dist, g_perm_dist);
    cudaGetSymbolAddress((void**)&st_rnn, g_starts_rnn);
    cudaGetSymbolAddress((void**)&st_room, g_starts_room);
    cudaGetSymbolAddress((void**)&st_dist, g_starts_dist);

    static bool attr_set = false;
    if (!attr_set) {
        cudaFuncSetAttribute(tf32gemm_bias_relu,
                             cudaFuncAttributeMaxDynamicSharedMemorySize, SMEM_BYTES);
        attr_set = true;
    }

    // 1) routing
    route_kernel<<<1, 256>>>(rnn_eid, n, 3, perm_rnn, st_rnn);
    route_kernel<<<1, 256>>>(room_eid, n, 2, perm_room, st_room);
    route_kernel<<<1, 256>>>(dist_eid, n, 2, perm_dist, st_dist);

    // 2) shared front-end GEMMs
    {
        dim3 g(FC / BN, 16384 / BM, 1);
        tf32gemm_bias_relu<<<g, 256, SMEM_BYTES>>>(cube, Wc, bc, hc, CUBE_K, FC, nullptr, nullptr);
    }
    {
        dim3 g(FC / BN, 6144 / BM, 1);
        tf32gemm_bias_relu<<<g, 256, SMEM_BYTES>>>(ego, Wd, bd, hd, EGO_K, FC, nullptr, nullptr);
    }

    // 3) x_dist elementwise
    xdist_kernel<<<n, 256>>>(hd, xd);

    // 4) routed layer-1 GEMMs
    {
        dim3 g(FC / BN, n / BM, 3);
        tf32gemm_bias_relu<<<g, 256, SMEM_BYTES>>>(rnn_feats, W1_rnn, b1_rnn, h_rnn, RNN2_K, FC, perm_rnn, st_rnn);
    }
    {
        dim3 g(FC / BN, n / BM, 2);
        tf32gemm_bias_relu<<<g, 256, SMEM_BYTES>>>(hc, W1_room, b1_room, h_room, ROOM_K, FC, perm_room, st_room);
    }
    {
        dim3 g(FC / BN, n / BM, 2);
        tf32gemm_bias_relu<<<g, 256, SMEM_BYTES>>>(xd, W1_dist, b1_dist, h_dist, DIST_K, FC, perm_dist, st_dist);
    }

    // 5) layer 2 + scatter
    layer2_kernel<<<n, 256>>>(h_rnn, W2_rnn, b2_rnn, perm_rnn, rnn_eid, out, 0);
    layer2_kernel<<<n, 256>>>(h_room, W2_room, b2_room, perm_room, room_eid, out, n);
    layer2_kernel<<<n, 256>>>(h_dist, W2_dist, b2_dist, perm_dist, dist_eid, out, 2 * n);
}